// round 4
// baseline (speedup 1.0000x reference)
#include <cuda_runtime.h>

#define D     64
#define EPSV  0.1f
#define MAXN  225000
#define MAXE  3200000

// Scratch (no allocations allowed).
__device__ float        g_xA[MAXN * D];
__device__ float        g_xB[MAXN * D];
__device__ unsigned int g_deg[MAXN];
__device__ int          g_rowptr[MAXN + 1];
__device__ int          g_cursor[MAXN];
__device__ int2         g_cw[MAXE];     // {src_col, weight_bits}

// ---------------------------------------------------------------------------
__global__ void zero_deg(int N) {
    int i = blockIdx.x * blockDim.x + threadIdx.x;
    if (i < N) g_deg[i] = 0u;
}

__global__ void deg_kernel(const int* __restrict__ dst, int E) {
    int e = blockIdx.x * blockDim.x + threadIdx.x;
    if (e < E) atomicAdd(&g_deg[dst[e]], 1u);
}

// ---------------------------------------------------------------------------
// Single-block exclusive scan of g_deg -> g_rowptr / g_cursor.
// Each thread owns a contiguous chunk; 3 phases: sum, block-scan, rescan.
// ---------------------------------------------------------------------------
__global__ void scan_all(int N) {
    __shared__ unsigned sums[1024];
    int tid = threadIdx.x;
    int chunk = (N + 1023) >> 10;
    int beg = tid * chunk;
    int end = min(beg + chunk, N);
    if (end < beg) end = beg;

    unsigned s = 0;
    for (int i = beg; i < end; i++) s += g_deg[i];
    sums[tid] = s;
    __syncthreads();
    for (int off = 1; off < 1024; off <<= 1) {
        unsigned t = (tid >= off) ? sums[tid - off] : 0u;
        __syncthreads();
        sums[tid] += t;
        __syncthreads();
    }
    unsigned run = sums[tid] - s;     // exclusive prefix of this chunk
    for (int i = beg; i < end; i++) {
        g_rowptr[i] = (int)run;
        g_cursor[i] = (int)run;
        run += g_deg[i];
    }
    if (tid == 1023) g_rowptr[N] = (int)run;  // == E
}

// ---------------------------------------------------------------------------
// fill CSR: w = 1/sqrt(deg[s]*deg[d])  (endpoint degrees are always >= 1)
// ---------------------------------------------------------------------------
__global__ void fill_kernel(const int* __restrict__ src,
                            const int* __restrict__ dst, int E) {
    int e = blockIdx.x * blockDim.x + threadIdx.x;
    if (e >= E) return;
    int s = __ldg(src + e);
    int d = __ldg(dst + e);
    int pos = atomicAdd(&g_cursor[d], 1);
    float w = rsqrtf((float)(__ldg(g_deg + s) * __ldg(g_deg + d)));
    g_cw[pos] = make_int2(s, __float_as_int(w));
}

// ---------------------------------------------------------------------------
// Fused gather SpMM + noise perturbation + output accumulation.
// Half-warp per node (16 lanes x float4); 2 nodes per warp.
// Layer 0 reads directly from Gu/Gi (no init copy).
// ---------------------------------------------------------------------------
__device__ __forceinline__ float sgnf(float v) {
    return (v > 0.f) ? 1.f : ((v < 0.f) ? -1.f : 0.f);
}

__global__ void gather_perturb(const float* __restrict__ Gu,
                               const float* __restrict__ Gi,
                               const float* __restrict__ noise,
                               float* __restrict__ acc,
                               int U, int N, int layer) {
    long long t = (long long)blockIdx.x * blockDim.x + threadIdx.x;
    int wi = (int)(t >> 5);
    int lane = threadIdx.x & 31;
    int half = lane >> 4;
    int hl = lane & 15;
    unsigned hmask = half ? 0xFFFF0000u : 0x0000FFFFu;
    int base = half << 4;
    int n = wi * 2 + half;
    if (n >= N) return;

    const float* x  = (layer & 1) ? g_xB : g_xA;
    float*       xn = (layer & 1) ? g_xA : g_xB;

    int beg = __ldg(g_rowptr + n);
    int end = __ldg(g_rowptr + n + 1);

    float4 s = make_float4(0.f, 0.f, 0.f, 0.f);
    for (int j0 = beg; j0 < end; j0 += 16) {
        int jj = j0 + hl;
        int2 cw = (jj < end) ? __ldg(g_cw + jj) : make_int2(0, 0);
        int cnt = min(16, end - j0);
        for (int k = 0; k < cnt; k++) {
            int   cc = __shfl_sync(hmask, cw.x, base + k);
            float ww = __int_as_float(__shfl_sync(hmask, cw.y, base + k));
            const float4* rp;
            if (layer == 0)
                rp = (cc < U) ? (const float4*)(Gu + (long long)cc * D)
                              : (const float4*)(Gi + (long long)(cc - U) * D);
            else
                rp = (const float4*)(x + (long long)cc * D);
            float4 v = __ldg(rp + hl);
            s.x += v.x * ww;
            s.y += v.y * ww;
            s.z += v.z * ww;
            s.w += v.w * ww;
        }
    }

    // perturb: s += sign(s) * (noise_row / max(||noise_row||,1e-12)) * EPS
    float4 nv = __ldg((const float4*)(noise + (long long)n * D) + hl);
    float ss = nv.x * nv.x + nv.y * nv.y + nv.z * nv.z + nv.w * nv.w;
    #pragma unroll
    for (int o = 8; o; o >>= 1) ss += __shfl_xor_sync(hmask, ss, o);
    float scale = EPSV / fmaxf(sqrtf(ss), 1e-12f);
    s.x += sgnf(s.x) * nv.x * scale;
    s.y += sgnf(s.y) * nv.y * scale;
    s.z += sgnf(s.z) * nv.z * scale;
    s.w += sgnf(s.w) * nv.w * scale;

    if (layer != 2)   // last layer's x_next is never read
        ((float4*)(xn + (long long)n * D))[hl] = s;

    const float third = 1.f / 3.f;
    float4* ap = (float4*)(acc + (long long)n * D) + hl;
    if (layer == 0) {
        *ap = make_float4(s.x * third, s.y * third, s.z * third, s.w * third);
    } else {
        float4 av = *ap;
        av.x += s.x * third;
        av.y += s.y * third;
        av.z += s.z * third;
        av.w += s.w * third;
        *ap = av;
    }
}

// ---------------------------------------------------------------------------
extern "C" void kernel_launch(void* const* d_in, const int* in_sizes, int n_in,
                              void* d_out, int out_size) {
    const float* Gu = (const float*)d_in[0];
    const float* Gi = (const float*)d_in[1];
    const float* nz = (const float*)d_in[2];
    const int*   ei = (const int*)d_in[3];

    int U = in_sizes[0] / D;
    int I = in_sizes[1] / D;
    int N = U + I;
    int E = in_sizes[3] / 2;

    const int* src = ei;
    const int* dst = ei + E;
    float* acc = (float*)d_out;

    const int TPB = 256;
    int blks_N = (N + TPB - 1) / TPB;
    int blks_E = (E + TPB - 1) / TPB;
    long long warp_threads = ((long long)(N + 1) / 2) * 32;
    int blks_g = (int)((warp_threads + TPB - 1) / TPB);

    zero_deg<<<blks_N, TPB>>>(N);                 // launch 0
    deg_kernel<<<blks_E, TPB>>>(dst, E);          // launch 1
    scan_all<<<1, 1024>>>(N);                     // launch 2
    fill_kernel<<<blks_E, TPB>>>(src, dst, E);    // launch 3

    for (int layer = 0; layer < 3; layer++)       // launches 4,5,6
        gather_perturb<<<blks_g, TPB>>>(Gu, Gi,
                                        nz + (long long)layer * N * D,
                                        acc, U, N, layer);
}